// round 1
// baseline (speedup 1.0000x reference)
#include <cuda_runtime.h>
#include <stdint.h>

#define BATCH 16
#define NPTS  131072
#define NSAMP 1024
#define BPB   8                      // blocks per batch
#define PTS   (NPTS / BPB)           // 16384 points per block
#define TH    512                    // threads per block
#define KK    (PTS / (4 * TH))       // 8 float4 chunks per thread
#define SMEM_BYTES (PTS * 3 * (int)sizeof(float))   // 196608

#define OFF_SCALE (BATCH * NSAMP * 3)   // 49152
#define OFF_IDX   (OFF_SCALE + BATCH)   // 49168

// device scratch (no allocations allowed)
__device__ float4   g_cand[2][BATCH][BPB][2];  // {v, idx_bits, x, y} {z,...}
__device__ unsigned g_cnt[BATCH];
__device__ int      g_idx[BATCH * NSAMP];
__device__ float    g_scale[BATCH];

// ---------------------------------------------------------------------------
// Kernel 1: centroid mean + object scale, also resets per-batch barrier ctrs
// ---------------------------------------------------------------------------
__global__ void __launch_bounds__(1024, 1)
scale_kernel(const float* __restrict__ mesh, float* __restrict__ out)
{
    const int b = blockIdx.x;
    const int tid = threadIdx.x;
    const float* mb = mesh + (size_t)b * NPTS * 3;

    float sx = 0.f, sy = 0.f, sz = 0.f;
    for (int p = tid; p < NPTS; p += 1024) {
        const float* q = mb + (size_t)p * 3;
        sx += q[0]; sy += q[1]; sz += q[2];
    }
    __shared__ float red[3][32];
    #pragma unroll
    for (int off = 16; off; off >>= 1) {
        sx += __shfl_xor_sync(0xffffffffu, sx, off);
        sy += __shfl_xor_sync(0xffffffffu, sy, off);
        sz += __shfl_xor_sync(0xffffffffu, sz, off);
    }
    const int w = tid >> 5, l = tid & 31;
    if (l == 0) { red[0][w] = sx; red[1][w] = sy; red[2][w] = sz; }
    __syncthreads();
    if (w == 0) {
        sx = red[0][l]; sy = red[1][l]; sz = red[2][l];
        #pragma unroll
        for (int off = 16; off; off >>= 1) {
            sx += __shfl_xor_sync(0xffffffffu, sx, off);
            sy += __shfl_xor_sync(0xffffffffu, sy, off);
            sz += __shfl_xor_sync(0xffffffffu, sz, off);
        }
        if (l == 0) {   // 1/NPTS is a power of two -> exact scaling
            red[0][0] = sx * (1.0f / NPTS);
            red[1][0] = sy * (1.0f / NPTS);
            red[2][0] = sz * (1.0f / NPTS);
        }
    }
    __syncthreads();
    const float cx = red[0][0], cy = red[1][0], cz = red[2][0];

    float m = 0.f;
    for (int p = tid; p < NPTS; p += 1024) {
        const float* q = mb + (size_t)p * 3;
        float dx = q[0] - cx, dy = q[1] - cy, dz = q[2] - cz;
        m = fmaxf(m, dx * dx + dy * dy + dz * dz);
    }
    #pragma unroll
    for (int off = 16; off; off >>= 1)
        m = fmaxf(m, __shfl_xor_sync(0xffffffffu, m, off));
    __syncthreads();
    if (l == 0) red[0][w] = m;
    __syncthreads();
    if (w == 0) {
        m = red[0][l];
        #pragma unroll
        for (int off = 16; off; off >>= 1)
            m = fmaxf(m, __shfl_xor_sync(0xffffffffu, m, off));
        if (l == 0) {
            float sc = __fsqrt_rn(m);       // sqrt(max) == max(sqrt): monotone
            g_scale[b] = sc;
            out[OFF_SCALE + b] = sc;
            g_cnt[b] = 0;                    // reset FPS barrier counter
        }
    }
}

// ---------------------------------------------------------------------------
// Kernel 2: farthest point sampling.  8 cooperating blocks per batch.
// ---------------------------------------------------------------------------

// distance in XLA's association order, no FMA contraction (fast-math immune)
__device__ __forceinline__ float dist3(float px, float py, float pz,
                                       float cx, float cy, float cz)
{
    float dx = px - cx, dy = py - cy, dz = pz - cz;
    return __fadd_rn(__fadd_rn(__fmul_rn(dx, dx), __fmul_rn(dy, dy)),
                     __fmul_rn(dz, dz));
}

__global__ void __launch_bounds__(TH, 1)
fps_kernel(const float* __restrict__ mesh, const int* __restrict__ finit)
{
    extern __shared__ float sm[];
    float* sx = sm;
    float* sy = sm + PTS;
    float* sz = sm + 2 * PTS;

    const int blk = blockIdx.x;
    const int b = blk / BPB;
    const int s = blk - b * BPB;
    const int tid = threadIdx.x;

    const float* mb = mesh + (size_t)b * NPTS * 3;

    // stage this block's xyz slice into SMEM (SoA, one-time)
    {
        const float* gsrc = mb + (size_t)s * PTS * 3;
        for (int e = tid; e < PTS * 3; e += TH) {
            float v = gsrc[e];
            int p = e / 3;
            int c = e - 3 * p;
            sm[c * PTS + p] = v;
        }
    }

    float4 dist[KK];
    #pragma unroll
    for (int k = 0; k < KK; k++)
        dist[k] = make_float4(1e10f, 1e10f, 1e10f, 1e10f);

    int fidx = finit[b];
    float cx = mb[(size_t)fidx * 3 + 0];
    float cy = mb[(size_t)fidx * 3 + 1];
    float cz = mb[(size_t)fidx * 3 + 2];

    __shared__ float rv[TH / 32];
    __shared__ int   rp[TH / 32];

    __syncthreads();

    const float4* sx4 = (const float4*)sx;
    const float4* sy4 = (const float4*)sy;
    const float4* sz4 = (const float4*)sz;

    for (int t = 0; t < NSAMP; ++t) {
        if (s == 0 && tid == 0) g_idx[b * NSAMP + t] = fidx;   // record BEFORE update
        if (t == NSAMP - 1) break;

        float bv = -1.0f;
        int   bp = 0x7fffffff;

        #pragma unroll
        for (int k = 0; k < KK; k++) {
            const int c = k * TH + tid;
            float4 px = sx4[c];
            float4 py = sy4[c];
            float4 pz = sz4[c];
            const int pbase = s * PTS + 4 * c;   // global-in-batch point index
            {   float d = dist3(px.x, py.x, pz.x, cx, cy, cz);
                float nd = fminf(dist[k].x, d); dist[k].x = nd;
                if (nd > bv) { bv = nd; bp = pbase + 0; } }
            {   float d = dist3(px.y, py.y, pz.y, cx, cy, cz);
                float nd = fminf(dist[k].y, d); dist[k].y = nd;
                if (nd > bv) { bv = nd; bp = pbase + 1; } }
            {   float d = dist3(px.z, py.z, pz.z, cx, cy, cz);
                float nd = fminf(dist[k].z, d); dist[k].z = nd;
                if (nd > bv) { bv = nd; bp = pbase + 2; } }
            {   float d = dist3(px.w, py.w, pz.w, cx, cy, cz);
                float nd = fminf(dist[k].w, d); dist[k].w = nd;
                if (nd > bv) { bv = nd; bp = pbase + 3; } }
        }

        // warp argmax (value desc, index asc on ties -> matches jnp.argmax)
        #pragma unroll
        for (int off = 16; off; off >>= 1) {
            float ov = __shfl_down_sync(0xffffffffu, bv, off);
            int   op = __shfl_down_sync(0xffffffffu, bp, off);
            if (ov > bv || (ov == bv && op < bp)) { bv = ov; bp = op; }
        }
        const int w = tid >> 5, l = tid & 31;
        if (l == 0) { rv[w] = bv; rp[w] = bp; }
        __syncthreads();
        if (w == 0) {
            bv = (l < TH / 32) ? rv[l] : -2.0f;
            bp = (l < TH / 32) ? rp[l] : 0x7fffffff;
            #pragma unroll
            for (int off = 8; off; off >>= 1) {
                float ov = __shfl_down_sync(0xffffffffu, bv, off);
                int   op = __shfl_down_sync(0xffffffffu, bp, off);
                if (ov > bv || (ov == bv && op < bp)) { bv = ov; bp = op; }
            }
            if (l == 0) {
                const int lp = bp - s * PTS;     // local index -> coords from SMEM
                const int par = t & 1;
                g_cand[par][b][s][0] = make_float4(bv, __int_as_float(bp), sx[lp], sy[lp]);
                g_cand[par][b][s][1] = make_float4(sz[lp], 0.f, 0.f, 0.f);
                __threadfence();                           // release
                atomicAdd(&g_cnt[b], 1u);                  // arrive
                const unsigned target = (unsigned)(BPB * (t + 1));
                volatile unsigned* cp = &g_cnt[b];         // L1-bypassing poll
                while (*cp < target) { }
            }
        }
        __syncthreads();

        // every block merges the 8 candidates identically (L2 reads via ldcg)
        const int par = t & 1;
        float mv = -1.0f; int mp = 0x7fffffff;
        float mx = 0.f, my = 0.f, mz = 0.f;
        #pragma unroll
        for (int i = 0; i < BPB; i++) {
            float4 a  = __ldcg(&g_cand[par][b][i][0]);
            float4 bb = __ldcg(&g_cand[par][b][i][1]);
            int p = __float_as_int(a.y);
            if (a.x > mv || (a.x == mv && p < mp)) {
                mv = a.x; mp = p; mx = a.z; my = a.w; mz = bb.x;
            }
        }
        fidx = mp; cx = mx; cy = my; cz = mz;
    }
}

// ---------------------------------------------------------------------------
// Kernel 3: gather sampled points, normalize, emit idx as float
// ---------------------------------------------------------------------------
__global__ void __launch_bounds__(1024, 1)
gather_kernel(const float* __restrict__ mesh, float* __restrict__ out)
{
    const int b = blockIdx.x;
    const int j = threadIdx.x;
    const int i = g_idx[b * NSAMP + j];
    const float sc = g_scale[b];
    const float* q = mesh + ((size_t)b * NPTS + (size_t)i) * 3;
    const size_t o = ((size_t)b * NSAMP + j) * 3;
    out[o + 0] = __fdiv_rn(q[0], sc);
    out[o + 1] = __fdiv_rn(q[1], sc);
    out[o + 2] = __fdiv_rn(q[2], sc);
    out[OFF_IDX + b * NSAMP + j] = (float)i;   // exact: i < 2^24
}

// ---------------------------------------------------------------------------
extern "C" void kernel_launch(void* const* d_in, const int* in_sizes, int n_in,
                              void* d_out, int out_size)
{
    const float* mesh  = (const float*)d_in[0];
    const int*   finit = (const int*)d_in[1];
    float* out = (float*)d_out;

    cudaFuncSetAttribute(fps_kernel,
                         cudaFuncAttributeMaxDynamicSharedMemorySize, SMEM_BYTES);

    scale_kernel<<<BATCH, 1024>>>(mesh, out);                 // also resets g_cnt
    fps_kernel<<<BATCH * BPB, TH, SMEM_BYTES>>>(mesh, finit); // 128 blocks <= 148 SMs
    gather_kernel<<<BATCH, 1024>>>(mesh, out);
}